// round 3
// baseline (speedup 1.0000x reference)
#include <cuda_runtime.h>
#include <math.h>

// ---------------- problem constants ----------------
constexpr int Bsz = 4;
constexpr int S   = 2048;
constexpr int D   = 1024;
constexpr int H   = 16;
constexpr int HD  = 64;        // head dim
constexpr int TD  = 3 * D;     // 3072
constexpr int M   = Bsz * S;   // 8192 rows

// ---------------- scratch (no allocations allowed) ----------------
__device__ float g_qkv[(size_t)Bsz * S * TD];   // [B*S, 3D]  (~100 MB)
__device__ float g_attn[(size_t)Bsz * S * D];   // [B*S, D]   (~33 MB)

// =====================================================================
// SGEMM + bias:  C[M,N] = A[M,K] @ B[K,N] + bias[N]
// 128x128 tile, BK=8, 256 threads, 8x8 per thread (2x2 blocks of 4x4).
// =====================================================================
__global__ __launch_bounds__(256) void sgemm_bias_kernel(
    const float* __restrict__ A, const float* __restrict__ B,
    const float* __restrict__ bias, float* __restrict__ C,
    int Mm, int N, int K)
{
    __shared__ float As[8][132];   // transposed A tile, padded
    __shared__ float Bs[8][128];

    const int tid = threadIdx.x;
    const int tx = tid & 15, ty = tid >> 4;
    const int bm = blockIdx.y * 128, bn = blockIdx.x * 128;

    float acc[8][8];
#pragma unroll
    for (int i = 0; i < 8; i++)
#pragma unroll
        for (int j = 0; j < 8; j++) acc[i][j] = 0.0f;

    const int arow = tid >> 1;          // 0..127
    const int acol = (tid & 1) * 4;     // 0 or 4
    const int brow = tid >> 5;          // 0..7
    const int bcol = (tid & 31) * 4;    // 0..124

    const float* Ap = A + (size_t)(bm + arow) * K + acol;
    const float* Bp = B + (size_t)brow * N + bn + bcol;

    for (int k0 = 0; k0 < K; k0 += 8) {
        float4 a4 = *(const float4*)Ap;
        float4 b4 = *(const float4*)Bp;
        As[acol + 0][arow] = a4.x;
        As[acol + 1][arow] = a4.y;
        As[acol + 2][arow] = a4.z;
        As[acol + 3][arow] = a4.w;
        *(float4*)&Bs[brow][bcol] = b4;
        __syncthreads();

#pragma unroll
        for (int kk = 0; kk < 8; kk++) {
            float ra[8], rb[8];
            *(float4*)&ra[0] = *(float4*)&As[kk][ty * 4];
            *(float4*)&ra[4] = *(float4*)&As[kk][ty * 4 + 64];
            *(float4*)&rb[0] = *(float4*)&Bs[kk][tx * 4];
            *(float4*)&rb[4] = *(float4*)&Bs[kk][tx * 4 + 64];
#pragma unroll
            for (int i = 0; i < 8; i++)
#pragma unroll
                for (int j = 0; j < 8; j++)
                    acc[i][j] = fmaf(ra[i], rb[j], acc[i][j]);
        }
        __syncthreads();
        Ap += 8;
        Bp += (size_t)8 * N;
    }

#pragma unroll
    for (int i = 0; i < 8; i++) {
        const int r = bm + ty * 4 + (i & 3) + (i >> 2) * 64;
#pragma unroll
        for (int jh = 0; jh < 2; jh++) {
            const int c = bn + tx * 4 + jh * 64;
            float4 o;
            o.x = acc[i][jh * 4 + 0] + bias[c + 0];
            o.y = acc[i][jh * 4 + 1] + bias[c + 1];
            o.z = acc[i][jh * 4 + 2] + bias[c + 2];
            o.w = acc[i][jh * 4 + 3] + bias[c + 3];
            *(float4*)&C[(size_t)r * N + c] = o;
        }
    }
}

// =====================================================================
// Causal flash attention, fp32.
// Block: 256 threads (16x16), handles 64 query rows of one (b,h).
// Thread (tx,ty): score frag rows ty*4+i, cols tx+16*j;
//                 output frag rows ty*4+i, dims tx*4+j.
// =====================================================================
constexpr int ATTN_SMEM = 4 * 64 * 68 * 4;   // Qs,Ks,Vs,Ps  = 69632 B

__global__ __launch_bounds__(256) void attn_kernel(
    const float* __restrict__ qkv, float* __restrict__ outp)
{
    extern __shared__ float sm[];
    float (*Qs)[68] = (float(*)[68])(sm);
    float (*Ks)[68] = (float(*)[68])(sm + 64 * 68);
    float (*Vs)[68] = (float(*)[68])(sm + 2 * 64 * 68);
    float (*Ps)[68] = (float(*)[68])(sm + 3 * 64 * 68);

    const int qt = (gridDim.x - 1) - blockIdx.x;  // heavy tiles launch first
    const int h  = blockIdx.y;
    const int b  = blockIdx.z;
    const int tid = threadIdx.x;
    const int tx = tid & 15, ty = tid >> 4;

    const float* qb = qkv + (size_t)b * S * TD + (size_t)h * HD;
    const float* kb = qb + D;
    const float* vb = qb + 2 * D;
    const int q0 = qt * 64;

    // load Q tile (coalesced: 16 threads per 64-float row)
    for (int i = tid; i < 64 * 16; i += 256) {
        const int r = i >> 4, c4 = (i & 15) << 2;
        *(float4*)&Qs[r][c4] = *(const float4*)(qb + (size_t)(q0 + r) * TD + c4);
    }

    float m[4], l[4], O[4][4];
#pragma unroll
    for (int i = 0; i < 4; i++) {
        m[i] = -1e30f; l[i] = 0.0f;
#pragma unroll
        for (int j = 0; j < 4; j++) O[i][j] = 0.0f;
    }

    for (int jt = 0; jt <= qt; ++jt) {
        const int k0 = jt * 64;
        __syncthreads();   // protect Ks/Vs/Ps from prior iteration's readers
        for (int i = tid; i < 64 * 16; i += 256) {
            const int r = i >> 4, c4 = (i & 15) << 2;
            *(float4*)&Ks[r][c4] = *(const float4*)(kb + (size_t)(k0 + r) * TD + c4);
            *(float4*)&Vs[r][c4] = *(const float4*)(vb + (size_t)(k0 + r) * TD + c4);
        }
        __syncthreads();

        // ---- S = Q @ K^T ----
        float s[4][4];
#pragma unroll
        for (int i = 0; i < 4; i++)
#pragma unroll
            for (int j = 0; j < 4; j++) s[i][j] = 0.0f;

#pragma unroll
        for (int kk = 0; kk < 64; kk += 4) {
            float4 a[4], bb[4];
#pragma unroll
            for (int i = 0; i < 4; i++) a[i]  = *(float4*)&Qs[ty * 4 + i][kk];
#pragma unroll
            for (int j = 0; j < 4; j++) bb[j] = *(float4*)&Ks[tx + 16 * j][kk];
#pragma unroll
            for (int i = 0; i < 4; i++)
#pragma unroll
                for (int j = 0; j < 4; j++) {
                    s[i][j] = fmaf(a[i].x, bb[j].x, s[i][j]);
                    s[i][j] = fmaf(a[i].y, bb[j].y, s[i][j]);
                    s[i][j] = fmaf(a[i].z, bb[j].z, s[i][j]);
                    s[i][j] = fmaf(a[i].w, bb[j].w, s[i][j]);
                }
        }

        // ---- scale + causal mask (matches reference: replace with -10000) ----
#pragma unroll
        for (int i = 0; i < 4; i++) {
            const int gr = q0 + ty * 4 + i;
#pragma unroll
            for (int j = 0; j < 4; j++) {
                float v = s[i][j] * 0.125f;        // 1/sqrt(64)
                const int gc = k0 + tx + 16 * j;
                if (gc > gr) v = -10000.0f;
                s[i][j] = v;
            }
        }

        // ---- streaming softmax ----
        float mt[4];
#pragma unroll
        for (int i = 0; i < 4; i++)
            mt[i] = fmaxf(fmaxf(s[i][0], s[i][1]), fmaxf(s[i][2], s[i][3]));
#pragma unroll
        for (int off = 1; off < 16; off <<= 1)
#pragma unroll
            for (int i = 0; i < 4; i++)
                mt[i] = fmaxf(mt[i], __shfl_xor_sync(0xffffffffu, mt[i], off));

        float mn[4], f[4], rs[4];
#pragma unroll
        for (int i = 0; i < 4; i++) mn[i] = fmaxf(m[i], mt[i]);
#pragma unroll
        for (int i = 0; i < 4; i++)
#pragma unroll
            for (int j = 0; j < 4; j++)
                s[i][j] = __expf(s[i][j] - mn[i]);
#pragma unroll
        for (int i = 0; i < 4; i++)
            rs[i] = (s[i][0] + s[i][1]) + (s[i][2] + s[i][3]);
#pragma unroll
        for (int off = 1; off < 16; off <<= 1)
#pragma unroll
            for (int i = 0; i < 4; i++)
                rs[i] += __shfl_xor_sync(0xffffffffu, rs[i], off);
#pragma unroll
        for (int i = 0; i < 4; i++) {
            f[i] = __expf(m[i] - mn[i]);
            l[i] = l[i] * f[i] + rs[i];
            m[i] = mn[i];
        }

        // write P and rescale O
#pragma unroll
        for (int i = 0; i < 4; i++)
#pragma unroll
            for (int j = 0; j < 4; j++)
                Ps[ty * 4 + i][tx + 16 * j] = s[i][j];
#pragma unroll
        for (int i = 0; i < 4; i++)
#pragma unroll
            for (int j = 0; j < 4; j++)
                O[i][j] *= f[i];
        __syncthreads();

        // ---- O += P @ V ----
#pragma unroll
        for (int kk = 0; kk < 64; kk += 4) {
            float4 p[4];
#pragma unroll
            for (int i = 0; i < 4; i++) p[i] = *(float4*)&Ps[ty * 4 + i][kk];
            const float4 v0 = *(float4*)&Vs[kk + 0][tx * 4];
            const float4 v1 = *(float4*)&Vs[kk + 1][tx * 4];
            const float4 v2 = *(float4*)&Vs[kk + 2][tx * 4];
            const float4 v3 = *(float4*)&Vs[kk + 3][tx * 4];
#pragma unroll
            for (int i = 0; i < 4; i++) {
                O[i][0] = fmaf(p[i].x, v0.x, fmaf(p[i].y, v1.x, fmaf(p[i].z, v2.x, fmaf(p[i].w, v3.x, O[i][0]))));
                O[i][1] = fmaf(p[i].x, v0.y, fmaf(p[i].y, v1.y, fmaf(p[i].z, v2.y, fmaf(p[i].w, v3.y, O[i][1]))));
                O[i][2] = fmaf(p[i].x, v0.z, fmaf(p[i].y, v1.z, fmaf(p[i].z, v2.z, fmaf(p[i].w, v3.z, O[i][2]))));
                O[i][3] = fmaf(p[i].x, v0.w, fmaf(p[i].y, v1.w, fmaf(p[i].z, v2.w, fmaf(p[i].w, v3.w, O[i][3]))));
            }
        }
    }

    // ---- epilogue: normalize + write [B,S,D] merged-head layout ----
#pragma unroll
    for (int i = 0; i < 4; i++) {
        const float inv = 1.0f / l[i];
        const int gr = q0 + ty * 4 + i;
        float4 o;
        o.x = O[i][0] * inv; o.y = O[i][1] * inv;
        o.z = O[i][2] * inv; o.w = O[i][3] * inv;
        *(float4*)&outp[(size_t)(b * S + gr) * D + h * HD + tx * 4] = o;
    }
}

// =====================================================================
// launch
// =====================================================================
extern "C" void kernel_launch(void* const* d_in, const int* in_sizes, int n_in,
                              void* d_out, int out_size)
{
    const float* hs     = (const float*)d_in[0];
    const float* w_attn = (const float*)d_in[1];
    const float* b_attn = (const float*)d_in[2];
    const float* w_proj = (const float*)d_in[3];
    const float* b_proj = (const float*)d_in[4];
    float* out = (float*)d_out;

    float *qkv, *attn;
    cudaGetSymbolAddress((void**)&qkv,  g_qkv);
    cudaGetSymbolAddress((void**)&attn, g_attn);
    cudaFuncSetAttribute(attn_kernel,
                         cudaFuncAttributeMaxDynamicSharedMemorySize, ATTN_SMEM);

    // 1) QKV projection: [8192,1024] @ [1024,3072] + b_attn
    dim3 g1(TD / 128, M / 128);        // (24, 64)
    sgemm_bias_kernel<<<g1, 256>>>(hs, w_attn, b_attn, qkv, M, TD, D);

    // 2) causal attention per (b, h, q-tile)
    dim3 g2(S / 64, H, Bsz);           // (32, 16, 4)
    attn_kernel<<<g2, 256, ATTN_SMEM>>>(qkv, attn);

    // 3) output projection: [8192,1024] @ [1024,1024] + b_proj
    dim3 g3(D / 128, M / 128);         // (8, 64)
    sgemm_bias_kernel<<<g3, 256>>>(attn, w_proj, b_proj, out, M, D, D);
}

// round 7
// speedup vs baseline: 1.2650x; 1.2650x over previous
#include <cuda_runtime.h>
#include <cuda_bf16.h>
#include <math.h>
#include <cstdint>

// ---------------- problem constants ----------------
constexpr int Bsz = 4;
constexpr int S   = 2048;
constexpr int D   = 1024;
constexpr int H   = 16;
constexpr int HD  = 64;
constexpr int TD  = 3 * D;     // 3072
constexpr int M   = Bsz * S;   // 8192

// ---------------- scratch (no allocations allowed) ----------------
__device__ float g_qkv[(size_t)M * TD];            // 96 MB
__device__ float g_attn[(size_t)M * D];            // 32 MB
__device__ __nv_bfloat16 g_Ah[(size_t)M * D];      // 16 MB
__device__ __nv_bfloat16 g_Al[(size_t)M * D];      // 16 MB
__device__ __nv_bfloat16 g_Bh[(size_t)TD * D];     //  6 MB (transposed [N][K])
__device__ __nv_bfloat16 g_Bl[(size_t)TD * D];     //  6 MB

// =====================================================================
// helpers
// =====================================================================
__device__ __forceinline__ uint32_t smem_u32(const void* p) {
    uint32_t a;
    asm("{ .reg .u64 t; cvta.to.shared.u64 t, %1; cvt.u32.u64 %0, t; }"
        : "=r"(a) : "l"(p));
    return a;
}
__device__ __forceinline__ void cp16(uint32_t s, const void* g) {
    asm volatile("cp.async.cg.shared.global [%0], [%1], 16;" :: "r"(s), "l"(g));
}
__device__ __forceinline__ void ldm4(uint32_t* r, uint32_t addr) {
    asm volatile("ldmatrix.sync.aligned.m8n8.x4.shared.b16 {%0,%1,%2,%3}, [%4];"
                 : "=r"(r[0]), "=r"(r[1]), "=r"(r[2]), "=r"(r[3]) : "r"(addr));
}
__device__ __forceinline__ void mma16816(float* c, const uint32_t* a, const uint32_t* b) {
    asm volatile(
        "mma.sync.aligned.m16n8k16.row.col.f32.bf16.bf16.f32 "
        "{%0,%1,%2,%3}, {%4,%5,%6,%7}, {%8,%9}, {%0,%1,%2,%3};"
        : "+f"(c[0]), "+f"(c[1]), "+f"(c[2]), "+f"(c[3])
        : "r"(a[0]), "r"(a[1]), "r"(a[2]), "r"(a[3]), "r"(b[0]), "r"(b[1]));
}

// =====================================================================
// split fp32 -> bf16 hi/lo (elementwise, vectorized x4)
// =====================================================================
__global__ __launch_bounds__(256) void split_bf16_kernel(
    const float* __restrict__ in,
    __nv_bfloat16* __restrict__ hi, __nv_bfloat16* __restrict__ lo, int n4)
{
    const int i = blockIdx.x * blockDim.x + threadIdx.x;
    if (i >= n4) return;
    const float4 v = ((const float4*)in)[i];
    float f[4] = {v.x, v.y, v.z, v.w};
    __nv_bfloat16 h[4], l[4];
#pragma unroll
    for (int j = 0; j < 4; ++j) {
        h[j] = __float2bfloat16_rn(f[j]);
        l[j] = __float2bfloat16_rn(f[j] - __bfloat162float(h[j]));
    }
    ((__nv_bfloat162*)hi)[2 * i]     = __nv_bfloat162{h[0], h[1]};
    ((__nv_bfloat162*)hi)[2 * i + 1] = __nv_bfloat162{h[2], h[3]};
    ((__nv_bfloat162*)lo)[2 * i]     = __nv_bfloat162{l[0], l[1]};
    ((__nv_bfloat162*)lo)[2 * i + 1] = __nv_bfloat162{l[2], l[3]};
}

// =====================================================================
// transpose + split:  in [K][N] fp32  ->  hi/lo [N][K] bf16
// =====================================================================
__global__ __launch_bounds__(256) void transpose_split_kernel(
    const float* __restrict__ in,
    __nv_bfloat16* __restrict__ hi, __nv_bfloat16* __restrict__ lo, int K, int N)
{
    __shared__ float t[32][33];
    const int n0 = blockIdx.x * 32, k0 = blockIdx.y * 32;
    const int tx = threadIdx.x, ty = threadIdx.y;
#pragma unroll
    for (int j = 0; j < 4; ++j)
        t[ty + j * 8][tx] = in[(size_t)(k0 + ty + j * 8) * N + n0 + tx];
    __syncthreads();
#pragma unroll
    for (int j = 0; j < 4; ++j) {
        const int row = ty + j * 8;                 // local n
        const float v = t[tx][row];                 // = in[k0+tx][n0+row]
        const __nv_bfloat16 h = __float2bfloat16_rn(v);
        const __nv_bfloat16 l = __float2bfloat16_rn(v - __bfloat162float(h));
        hi[(size_t)(n0 + row) * K + k0 + tx] = h;
        lo[(size_t)(n0 + row) * K + k0 + tx] = l;
    }
}

// =====================================================================
// bf16x3 tensor-core GEMM + bias via mma.sync:
//   C[M,N] = A[M,K] @ B[K,N] + bias   with A as (Ah,Al)[M][K], B as (Bh,Bl)[N][K]
// CTA 128x128, BK=32, 256 threads (8 warps, 4x2 of 32x64 warp tiles),
// double-buffered cp.async, 80B-pitch smem rows (conflict-free ldmatrix).
// =====================================================================
constexpr int TSZ       = 128 * 80;          // 10240 B per operand tile
constexpr int BUFSZ     = 4 * TSZ;           // Ah|Al|Bh|Bl
constexpr int GEMM_SMEM = 2 * BUFSZ;         // 81920 B

__global__ __launch_bounds__(256) void gemm_bf16x3_kernel(
    const __nv_bfloat16* __restrict__ Ah, const __nv_bfloat16* __restrict__ Al,
    const __nv_bfloat16* __restrict__ Bh, const __nv_bfloat16* __restrict__ Bl,
    const float* __restrict__ bias, float* __restrict__ C, int N, int K)
{
    extern __shared__ char smem[];
    const uint32_t sb = smem_u32(smem);
    const int tid  = threadIdx.x;
    const int lane = tid & 31, wid = tid >> 5;
    const int wm = wid & 3, wn = wid >> 2;
    const int bm = blockIdx.y * 128, bn = blockIdx.x * 128;

    // ---- loader mapping: each thread owns 8 16B chunks (2 rows x 4 chunks) ----
    const int ltile = tid >> 6;                 // 0..3 : Ah,Al,Bh,Bl
    const int lrb   = (tid & 63) * 2;           // first of two rows
    const __nv_bfloat16* lgb =
        (ltile == 0) ? Ah : (ltile == 1) ? Al : (ltile == 2) ? Bh : Bl;
    const __nv_bfloat16* lg = lgb + (size_t)((ltile < 2 ? bm : bn) + lrb) * K;
    const uint32_t lsm = (uint32_t)(ltile * TSZ + lrb * 80);

#define ISSUE(buf, kt) do {                                                    \
    const __nv_bfloat16* _g = lg + (kt) * 32;                                  \
    const uint32_t _s = sb + (buf) * BUFSZ + lsm;                              \
    cp16(_s,       _g);      cp16(_s + 16,  _g + 8);                           \
    cp16(_s + 32,  _g + 16); cp16(_s + 48,  _g + 24);                          \
    cp16(_s + 80,  _g + K);      cp16(_s + 96,  _g + K + 8);                   \
    cp16(_s + 112, _g + K + 16); cp16(_s + 128, _g + K + 24);                  \
    asm volatile("cp.async.commit_group;" ::: "memory");                       \
} while (0)

    float acc[2][8][4];
#pragma unroll
    for (int a = 0; a < 2; ++a)
#pragma unroll
        for (int b = 0; b < 8; ++b)
#pragma unroll
            for (int c = 0; c < 4; ++c) acc[a][b][c] = 0.0f;

    // per-thread ldmatrix base offsets
    const uint32_t aoff = (uint32_t)((lane & 15) * 80 + (lane >> 4) * 16);
    const uint32_t boff = (uint32_t)(((lane & 7) + ((lane >> 4) << 3)) * 80 +
                                     ((lane >> 3) & 1) * 16);

    const int NT = K / 32;
    ISSUE(0, 0);

    for (int kt = 0; kt < NT; ++kt) {
        if (kt + 1 < NT) {
            ISSUE((kt + 1) & 1, kt + 1);
            asm volatile("cp.async.wait_group 1;" ::: "memory");
        } else {
            asm volatile("cp.async.wait_group 0;" ::: "memory");
        }
        __syncthreads();

        const uint32_t base = sb + (kt & 1) * BUFSZ;
        const uint32_t pAh = base + (uint32_t)(wm * 32 * 80) + aoff;
        const uint32_t pAl = pAh + TSZ;
        const uint32_t pBh = base + 2 * TSZ + (uint32_t)(wn * 64 * 80) + boff;
        const uint32_t pBl = pBh + TSZ;

#pragma unroll
        for (int ks = 0; ks < 2; ++ks) {
            const uint32_t ko = (uint32_t)(ks * 32);   // 16 bf16 = 32 B
            uint32_t ah[2][4], al[2][4], bh[4][4], bl[4][4];
            ldm4(ah[0], pAh + ko);        ldm4(ah[1], pAh + 1280 + ko);
            ldm4(al[0], pAl + ko);        ldm4(al[1], pAl + 1280 + ko);
#pragma unroll
            for (int g = 0; g < 4; ++g) {
                ldm4(bh[g], pBh + (uint32_t)(g * 1280) + ko);
                ldm4(bl[g], pBl + (uint32_t)(g * 1280) + ko);
            }
#pragma unroll
            for (int mi = 0; mi < 2; ++mi)
#pragma unroll
                for (int nj = 0; nj < 8; ++nj) {
                    const uint32_t* ph = &bh[nj >> 1][(nj & 1) * 2];
                    const uint32_t* pl = &bl[nj >> 1][(nj & 1) * 2];
                    mma16816(acc[mi][nj], ah[mi], ph);
                    mma16816(acc[mi][nj], ah[mi], pl);
                    mma16816(acc[mi][nj], al[mi], ph);
                }
        }
        __syncthreads();
    }
#undef ISSUE

    // ---- epilogue: bias + store fp32 ----
#pragma unroll
    for (int mi = 0; mi < 2; ++mi) {
        const int row0 = bm + wm * 32 + mi * 16 + (lane >> 2);
#pragma unroll
        for (int nj = 0; nj < 8; ++nj) {
            const int col = bn + wn * 64 + nj * 8 + (lane & 3) * 2;
            const float bx = bias[col], by = bias[col + 1];
            float2 v0, v1;
            v0.x = acc[mi][nj][0] + bx; v0.y = acc[mi][nj][1] + by;
            v1.x = acc[mi][nj][2] + bx; v1.y = acc[mi][nj][3] + by;
            *(float2*)&C[(size_t)row0 * N + col]       = v0;
            *(float2*)&C[(size_t)(row0 + 8) * N + col] = v1;
        }
    }
}

// =====================================================================
// Causal flash attention, fp32 SIMT (unchanged R3 passing version)
// =====================================================================
constexpr int ATTN_SMEM = 4 * 64 * 68 * 4;

__global__ __launch_bounds__(256) void attn_kernel(
    const float* __restrict__ qkv, float* __restrict__ outp)
{
    extern __shared__ float sm[];
    float (*Qs)[68] = (float(*)[68])(sm);
    float (*Ks)[68] = (float(*)[68])(sm + 64 * 68);
    float (*Vs)[68] = (float(*)[68])(sm + 2 * 64 * 68);
    float (*Ps)[68] = (float(*)[68])(sm + 3 * 64 * 68);

    const int qt = (gridDim.x - 1) - blockIdx.x;
    const int h  = blockIdx.y;
    const int b  = blockIdx.z;
    const int tid = threadIdx.x;
    const int tx = tid & 15, ty = tid >> 4;

    const float* qb = qkv + (size_t)b * S * TD + (size_t)h * HD;
    const float* kb = qb + D;
    const float* vb = qb + 2 * D;
    const int q0 = qt * 64;

    for (int i = tid; i < 64 * 16; i += 256) {
        const int r = i >> 4, c4 = (i & 15) << 2;
        *(float4*)&Qs[r][c4] = *(const float4*)(qb + (size_t)(q0 + r) * TD + c4);
    }

    float m[4], l[4], O[4][4];
#pragma unroll
    for (int i = 0; i < 4; i++) {
        m[i] = -1e30f; l[i] = 0.0f;
#pragma unroll
        for (int j = 0; j < 4; j++) O[i][j] = 0.0f;
    }

    for (int jt = 0; jt <= qt; ++jt) {
        const int k0 = jt * 64;
        __syncthreads();
        for (int i = tid; i < 64 * 16; i += 256) {
            const int r = i >> 4, c4 = (i & 15) << 2;
            *(float4*)&Ks[r][c4] = *(const float4*)(kb + (size_t)(k0 + r) * TD + c4);
            *(float4*)&Vs[r][c4] = *(const float4*)(vb + (size_t)(k0 + r) * TD + c4);
        }
        __syncthreads();

        float s[4][4];
#pragma unroll
        for (int i = 0; i < 4; i++)
#pragma unroll
            for (int j = 0; j < 4; j++) s[i][j] = 0.0f;

#pragma unroll
        for (int kk = 0; kk < 64; kk += 4) {
            float4 a[4], bb[4];
#pragma unroll
            for (int i = 0; i < 4; i++) a[i]  = *(float4*)&Qs[ty * 4 + i][kk];
#pragma unroll
            for (int j = 0; j < 4; j++) bb[j] = *(float4*)&Ks[tx + 16 * j][kk];
#pragma unroll
            for (int i = 0; i < 4; i++)
#pragma unroll
                for (int j = 0; j < 4; j++) {
                    s[i][j] = fmaf(a[i].x, bb[j].x, s[i][j]);
                    s[i][j] = fmaf(a[i].y, bb[j].y, s[i][j]);
                    s[i][j] = fmaf(a[i].z, bb[j].z, s[i][j]);
                    s[i][j] = fmaf(a[i].w, bb[j].w, s[i][j]);
                }
        }

#pragma unroll
        for (int i = 0; i < 4; i++) {
            const int gr = q0 + ty * 4 + i;
#pragma unroll
            for (int j = 0; j < 4; j++) {
                float v = s[i][j] * 0.125f;
                const int gc = k0 + tx + 16 * j;
                if (gc > gr) v = -10000.0f;
                s[i][j] = v;
            }
        }

        float mt[4];
#pragma unroll
        for (int i = 0; i < 4; i++)
            mt[i] = fmaxf(fmaxf(s[i][0], s[i][1]), fmaxf(s[i][2], s[i][3]));
#pragma unroll
        for (int off = 1; off < 16; off <<= 1)
#pragma unroll
            for (int i = 0; i < 4; i++)
                mt[i] = fmaxf(mt[i], __shfl_xor_sync(0xffffffffu, mt[i], off));

        float mn[4], f[4], rs[4];
#pragma unroll
        for (int i = 0; i < 4; i++) mn[i] = fmaxf(m[i], mt[i]);
#pragma unroll
        for (int i = 0; i < 4; i++)
#pragma unroll
            for (int j = 0; j < 4; j++)
                s[i][j] = __expf(s[i][j] - mn[i]);
#pragma unroll
        for (int i = 0; i < 4; i++)
            rs[i] = (s[i][0] + s[i][1]) + (s[i][2] + s[i][3]);
#pragma unroll
        for (int off = 1; off < 16; off <<= 1)
#pragma unroll
            for (int i = 0; i < 4; i++)
                rs[i] += __shfl_xor_sync(0xffffffffu, rs[i], off);
#pragma unroll
        for (int i = 0; i < 4; i++) {
            f[i] = __expf(m[i] - mn[i]);
            l[i] = l[i] * f[i] + rs[i];
            m[i] = mn[i];
        }

#pragma unroll
        for (int i = 0; i < 4; i++)
#pragma unroll
            for (int j = 0; j < 4; j++)
                Ps[ty * 4 + i][tx + 16 * j] = s[i][j];
#pragma unroll
        for (int i = 0; i < 4; i++)
#pragma unroll
            for (int j = 0; j < 4; j++)
                O[i][j] *= f[i];
        __syncthreads();

#pragma unroll
        for (int kk = 0; kk < 64; kk += 4) {
            float4 p[4];
#pragma unroll
            for (int i = 0; i < 4; i++) p[i] = *(float4*)&Ps[ty * 4 + i][kk];
            const float4 v0 = *(float4*)&Vs[kk + 0][tx * 4];
            const float4 v1 = *(float4*)&Vs[kk + 1][tx * 4];
            const float4 v2 = *(float4*)&Vs[kk + 2][tx * 4];
            const float4 v3 = *(float4*)&Vs[kk + 3][tx * 4];
#pragma unroll
            for (int i = 0; i < 4; i++) {
                O[i][0] = fmaf(p[i].x, v0.x, fmaf(p[i].y, v1.x, fmaf(p[i].z, v2.x, fmaf(p[i].w, v3.x, O[i][0]))));
                O[i][1] = fmaf(p[i].x, v0.y, fmaf(p[i].y, v1.y, fmaf(p[i].z, v2.y, fmaf(p[i].w, v3.y, O[i][1]))));
                O[i][2] = fmaf(p[i].x, v0.z, fmaf(p[i].y, v1.z, fmaf(p[i].z, v2.z, fmaf(p[i].w, v3.z, O[i][2]))));
                O[i][3] = fmaf(p[i].x, v0.w, fmaf(p[i].y, v1.w, fmaf(p[i].z, v2.w, fmaf(p[i].w, v3.w, O[i][3]))));
            }
        }
    }

#pragma unroll
    for (int i = 0; i < 4; i++) {
        const float inv = 1.0f / l[i];
        const int gr = q0 + ty * 4 + i;
        float4 o;
        o.x = O[i][0] * inv; o.y = O[i][1] * inv;
        o.z = O[i][2] * inv; o.w = O[i][3] * inv;
        *(float4*)&outp[(size_t)(b * S + gr) * D + h * HD + tx * 4] = o;
    }
}

// =====================================================================
// launch
// =====================================================================
extern "C" void kernel_launch(void* const* d_in, const int* in_sizes, int n_in,
                              void* d_out, int out_size)
{
    const float* hs     = (const float*)d_in[0];
    const float* w_attn = (const float*)d_in[1];
    const float* b_attn = (const float*)d_in[2];
    const float* w_proj = (const float*)d_in[3];
    const float* b_proj = (const float*)d_in[4];
    float* out = (float*)d_out;

    float *qkv, *attn;
    __nv_bfloat16 *Ah, *Al, *Bh, *Bl;
    cudaGetSymbolAddress((void**)&qkv,  g_qkv);
    cudaGetSymbolAddress((void**)&attn, g_attn);
    cudaGetSymbolAddress((void**)&Ah, g_Ah);
    cudaGetSymbolAddress((void**)&Al, g_Al);
    cudaGetSymbolAddress((void**)&Bh, g_Bh);
    cudaGetSymbolAddress((void**)&Bl, g_Bl);

    cudaFuncSetAttribute(gemm_bf16x3_kernel,
                         cudaFuncAttributeMaxDynamicSharedMemorySize, GEMM_SMEM);
    cudaFuncSetAttribute(attn_kernel,
                         cudaFuncAttributeMaxDynamicSharedMemorySize, ATTN_SMEM);

    // --- stage 1: QKV projection ---
    split_bf16_kernel<<<(M * D / 4 + 255) / 256, 256>>>(hs, Ah, Al, M * D / 4);
    transpose_split_kernel<<<dim3(TD / 32, D / 32), dim3(32, 8)>>>(w_attn, Bh, Bl, D, TD);
    dim3 g1(TD / 128, M / 128);
    gemm_bf16x3_kernel<<<g1, 256, GEMM_SMEM>>>(Ah, Al, Bh, Bl, b_attn, qkv, TD, D);

    // --- stage 2: causal attention ---
    dim3 g2(S / 64, H, Bsz);
    attn_kernel<<<g2, 256, ATTN_SMEM>>>(qkv, attn);

    // --- stage 3: output projection ---
    split_bf16_kernel<<<(M * D / 4 + 255) / 256, 256>>>(attn, Ah, Al, M * D / 4);
    transpose_split_kernel<<<dim3(D / 32, D / 32), dim3(32, 8)>>>(w_proj, Bh, Bl, D, D);
    dim3 g3(D / 128, M / 128);
    gemm_bf16x3_kernel<<<g3, 256, GEMM_SMEM>>>(Ah, Al, Bh, Bl, b_proj, out, D, D);
}

// round 8
// speedup vs baseline: 1.8248x; 1.4426x over previous
#include <cuda_runtime.h>
#include <cuda_bf16.h>
#include <math.h>
#include <cstdint>

// ---------------- problem constants ----------------
constexpr int Bsz = 4;
constexpr int S   = 2048;
constexpr int D   = 1024;
constexpr int H   = 16;
constexpr int HD  = 64;
constexpr int TD  = 3 * D;     // 3072
constexpr int M   = Bsz * S;   // 8192

// ---------------- scratch (no allocations allowed) ----------------
__device__ float g_qkv[(size_t)M * TD];            // 96 MB
__device__ __nv_bfloat16 g_Ah[(size_t)M * D];      // 16 MB
__device__ __nv_bfloat16 g_Al[(size_t)M * D];      // 16 MB
__device__ __nv_bfloat16 g_Bh[(size_t)TD * D];     //  6 MB (transposed [N][K])
__device__ __nv_bfloat16 g_Bl[(size_t)TD * D];     //  6 MB

// =====================================================================
// helpers
// =====================================================================
__device__ __forceinline__ uint32_t smem_u32(const void* p) {
    uint32_t a;
    asm("{ .reg .u64 t; cvta.to.shared.u64 t, %1; cvt.u32.u64 %0, t; }"
        : "=r"(a) : "l"(p));
    return a;
}
__device__ __forceinline__ void cp16(uint32_t s, const void* g) {
    asm volatile("cp.async.cg.shared.global [%0], [%1], 16;" :: "r"(s), "l"(g));
}
__device__ __forceinline__ void ldm4(uint32_t* r, uint32_t addr) {
    asm volatile("ldmatrix.sync.aligned.m8n8.x4.shared.b16 {%0,%1,%2,%3}, [%4];"
                 : "=r"(r[0]), "=r"(r[1]), "=r"(r[2]), "=r"(r[3]) : "r"(addr));
}
__device__ __forceinline__ void ldm4t(uint32_t* r, uint32_t addr) {
    asm volatile("ldmatrix.sync.aligned.m8n8.x4.trans.shared.b16 {%0,%1,%2,%3}, [%4];"
                 : "=r"(r[0]), "=r"(r[1]), "=r"(r[2]), "=r"(r[3]) : "r"(addr));
}
__device__ __forceinline__ void mma16816(float* c, const uint32_t* a, const uint32_t* b) {
    asm volatile(
        "mma.sync.aligned.m16n8k16.row.col.f32.bf16.bf16.f32 "
        "{%0,%1,%2,%3}, {%4,%5,%6,%7}, {%8,%9}, {%0,%1,%2,%3};"
        : "+f"(c[0]), "+f"(c[1]), "+f"(c[2]), "+f"(c[3])
        : "r"(a[0]), "r"(a[1]), "r"(a[2]), "r"(a[3]), "r"(b[0]), "r"(b[1]));
}
// pack two fp32 -> bf16x2 (a -> low half, b -> high half)
__device__ __forceinline__ uint32_t pack_bf(float a, float b) {
    uint32_t r;
    asm("cvt.rn.bf16x2.f32 %0, %1, %2;" : "=r"(r) : "f"(b), "f"(a));
    return r;
}
// residual of (a,b) after subtracting bf16 parts already packed in hpk
__device__ __forceinline__ uint32_t pack_lo(uint32_t hpk, float a, float b) {
    const float al = a - __uint_as_float(hpk << 16);
    const float bl = b - __uint_as_float(hpk & 0xFFFF0000u);
    return pack_bf(al, bl);
}

// =====================================================================
// split fp32 -> bf16 hi/lo (elementwise, vectorized x4)
// =====================================================================
__global__ __launch_bounds__(256) void split_bf16_kernel(
    const float* __restrict__ in,
    __nv_bfloat16* __restrict__ hi, __nv_bfloat16* __restrict__ lo, int n4)
{
    const int i = blockIdx.x * blockDim.x + threadIdx.x;
    if (i >= n4) return;
    const float4 v = ((const float4*)in)[i];
    float f[4] = {v.x, v.y, v.z, v.w};
    __nv_bfloat16 h[4], l[4];
#pragma unroll
    for (int j = 0; j < 4; ++j) {
        h[j] = __float2bfloat16_rn(f[j]);
        l[j] = __float2bfloat16_rn(f[j] - __bfloat162float(h[j]));
    }
    ((__nv_bfloat162*)hi)[2 * i]     = __nv_bfloat162{h[0], h[1]};
    ((__nv_bfloat162*)hi)[2 * i + 1] = __nv_bfloat162{h[2], h[3]};
    ((__nv_bfloat162*)lo)[2 * i]     = __nv_bfloat162{l[0], l[1]};
    ((__nv_bfloat162*)lo)[2 * i + 1] = __nv_bfloat162{l[2], l[3]};
}

// =====================================================================
// transpose + split:  in [K][N] fp32  ->  hi/lo [N][K] bf16
// =====================================================================
__global__ __launch_bounds__(256) void transpose_split_kernel(
    const float* __restrict__ in,
    __nv_bfloat16* __restrict__ hi, __nv_bfloat16* __restrict__ lo, int K, int N)
{
    __shared__ float t[32][33];
    const int n0 = blockIdx.x * 32, k0 = blockIdx.y * 32;
    const int tx = threadIdx.x, ty = threadIdx.y;
#pragma unroll
    for (int j = 0; j < 4; ++j)
        t[ty + j * 8][tx] = in[(size_t)(k0 + ty + j * 8) * N + n0 + tx];
    __syncthreads();
#pragma unroll
    for (int j = 0; j < 4; ++j) {
        const int row = ty + j * 8;
        const float v = t[tx][row];
        const __nv_bfloat16 h = __float2bfloat16_rn(v);
        const __nv_bfloat16 l = __float2bfloat16_rn(v - __bfloat162float(h));
        hi[(size_t)(n0 + row) * K + k0 + tx] = h;
        lo[(size_t)(n0 + row) * K + k0 + tx] = l;
    }
}

// =====================================================================
// bf16x3 tensor-core GEMM + bias (unchanged from R7 passing version)
// =====================================================================
constexpr int TSZ       = 128 * 80;
constexpr int BUFSZ     = 4 * TSZ;
constexpr int GEMM_SMEM = 2 * BUFSZ;         // 81920 B

__global__ __launch_bounds__(256) void gemm_bf16x3_kernel(
    const __nv_bfloat16* __restrict__ Ah, const __nv_bfloat16* __restrict__ Al,
    const __nv_bfloat16* __restrict__ Bh, const __nv_bfloat16* __restrict__ Bl,
    const float* __restrict__ bias, float* __restrict__ C, int N, int K)
{
    extern __shared__ char smem[];
    const uint32_t sb = smem_u32(smem);
    const int tid  = threadIdx.x;
    const int lane = tid & 31, wid = tid >> 5;
    const int wm = wid & 3, wn = wid >> 2;
    const int bm = blockIdx.y * 128, bn = blockIdx.x * 128;

    const int ltile = tid >> 6;
    const int lrb   = (tid & 63) * 2;
    const __nv_bfloat16* lgb =
        (ltile == 0) ? Ah : (ltile == 1) ? Al : (ltile == 2) ? Bh : Bl;
    const __nv_bfloat16* lg = lgb + (size_t)((ltile < 2 ? bm : bn) + lrb) * K;
    const uint32_t lsm = (uint32_t)(ltile * TSZ + lrb * 80);

#define ISSUE(buf, kt) do {                                                    \
    const __nv_bfloat16* _g = lg + (kt) * 32;                                  \
    const uint32_t _s = sb + (buf) * BUFSZ + lsm;                              \
    cp16(_s,       _g);      cp16(_s + 16,  _g + 8);                           \
    cp16(_s + 32,  _g + 16); cp16(_s + 48,  _g + 24);                          \
    cp16(_s + 80,  _g + K);      cp16(_s + 96,  _g + K + 8);                   \
    cp16(_s + 112, _g + K + 16); cp16(_s + 128, _g + K + 24);                  \
    asm volatile("cp.async.commit_group;" ::: "memory");                       \
} while (0)

    float acc[2][8][4];
#pragma unroll
    for (int a = 0; a < 2; ++a)
#pragma unroll
        for (int b = 0; b < 8; ++b)
#pragma unroll
            for (int c = 0; c < 4; ++c) acc[a][b][c] = 0.0f;

    const uint32_t aoff = (uint32_t)((lane & 15) * 80 + (lane >> 4) * 16);
    const uint32_t boff = (uint32_t)(((lane & 7) + ((lane >> 4) << 3)) * 80 +
                                     ((lane >> 3) & 1) * 16);

    const int NT = K / 32;
    ISSUE(0, 0);

    for (int kt = 0; kt < NT; ++kt) {
        if (kt + 1 < NT) {
            ISSUE((kt + 1) & 1, kt + 1);
            asm volatile("cp.async.wait_group 1;" ::: "memory");
        } else {
            asm volatile("cp.async.wait_group 0;" ::: "memory");
        }
        __syncthreads();

        const uint32_t base = sb + (kt & 1) * BUFSZ;
        const uint32_t pAh = base + (uint32_t)(wm * 32 * 80) + aoff;
        const uint32_t pAl = pAh + TSZ;
        const uint32_t pBh = base + 2 * TSZ + (uint32_t)(wn * 64 * 80) + boff;
        const uint32_t pBl = pBh + TSZ;

#pragma unroll
        for (int ks = 0; ks < 2; ++ks) {
            const uint32_t ko = (uint32_t)(ks * 32);
            uint32_t ah[2][4], al[2][4], bh[4][4], bl[4][4];
            ldm4(ah[0], pAh + ko);        ldm4(ah[1], pAh + 1280 + ko);
            ldm4(al[0], pAl + ko);        ldm4(al[1], pAl + 1280 + ko);
#pragma unroll
            for (int g = 0; g < 4; ++g) {
                ldm4(bh[g], pBh + (uint32_t)(g * 1280) + ko);
                ldm4(bl[g], pBl + (uint32_t)(g * 1280) + ko);
            }
#pragma unroll
            for (int mi = 0; mi < 2; ++mi)
#pragma unroll
                for (int nj = 0; nj < 8; ++nj) {
                    const uint32_t* ph = &bh[nj >> 1][(nj & 1) * 2];
                    const uint32_t* pl = &bl[nj >> 1][(nj & 1) * 2];
                    mma16816(acc[mi][nj], ah[mi], ph);
                    mma16816(acc[mi][nj], ah[mi], pl);
                    mma16816(acc[mi][nj], al[mi], ph);
                }
        }
        __syncthreads();
    }
#undef ISSUE

#pragma unroll
    for (int mi = 0; mi < 2; ++mi) {
        const int row0 = bm + wm * 32 + mi * 16 + (lane >> 2);
#pragma unroll
        for (int nj = 0; nj < 8; ++nj) {
            const int col = bn + wn * 64 + nj * 8 + (lane & 3) * 2;
            const float bx = bias[col], by = bias[col + 1];
            float2 v0, v1;
            v0.x = acc[mi][nj][0] + bx; v0.y = acc[mi][nj][1] + by;
            v1.x = acc[mi][nj][2] + bx; v1.y = acc[mi][nj][3] + by;
            *(float2*)&C[(size_t)row0 * N + col]       = v0;
            *(float2*)&C[(size_t)(row0 + 8) * N + col] = v1;
        }
    }
}

// =====================================================================
// Causal flash attention via mma.sync bf16x3.
// CTA: 128 q-rows of one (b,h); 8 warps x 16 q-rows; k-tile 64.
// Smem tiles pitch 144B (72 bf16) -> conflict-free ldmatrix.
// Epilogue writes bf16 hi/lo split directly (feeds proj GEMM).
// =====================================================================
constexpr int APITCH = 144;                       // bytes per row
constexpr int ATTN2_SMEM = 73728;                 // Qh,Ql(128) + Kh,Kl,Vh,Vl(64)

__global__ __launch_bounds__(256) void attn_mma_kernel(
    const float* __restrict__ qkv,
    __nv_bfloat16* __restrict__ Ahd, __nv_bfloat16* __restrict__ Ald)
{
    extern __shared__ char smn[];
    const uint32_t sb = smem_u32(smn);
    const int tid = threadIdx.x, lane = tid & 31, wid = tid >> 5;
    const int qt = (gridDim.x - 1) - blockIdx.x;   // heavy tiles first
    const int h = blockIdx.y, b = blockIdx.z;
    const int q0 = qt * 128;

    const float* qb = qkv + (size_t)b * S * TD + h * HD;
    const float* kb = qb + D;
    const float* vb = qb + 2 * D;

    // smem byte offsets
    const uint32_t QH = 0, QL = 18432, KH = 36864, KL = 46080, VH = 55296, VL = 64512;
    char* const smc = smn;

    // ---- load + split Q tile (128 x 64) ----
    for (int i = tid; i < 128 * 16; i += 256) {
        const int r = i >> 4, c4 = (i & 15) << 2;
        const float4 v = *(const float4*)(qb + (size_t)(q0 + r) * TD + c4);
        const uint32_t off = (uint32_t)(r * APITCH + c4 * 2);
        const __nv_bfloat16 h0 = __float2bfloat16_rn(v.x), h1 = __float2bfloat16_rn(v.y),
                            h2 = __float2bfloat16_rn(v.z), h3 = __float2bfloat16_rn(v.w);
        *(__nv_bfloat162*)(smc + QH + off)     = __nv_bfloat162{h0, h1};
        *(__nv_bfloat162*)(smc + QH + off + 4) = __nv_bfloat162{h2, h3};
        *(__nv_bfloat162*)(smc + QL + off)     = __nv_bfloat162{
            __float2bfloat16_rn(v.x - __bfloat162float(h0)),
            __float2bfloat16_rn(v.y - __bfloat162float(h1))};
        *(__nv_bfloat162*)(smc + QL + off + 4) = __nv_bfloat162{
            __float2bfloat16_rn(v.z - __bfloat162float(h2)),
            __float2bfloat16_rn(v.w - __bfloat162float(h3))};
    }

    // fragment address offsets
    const uint32_t aoff = (uint32_t)((lane & 15) * APITCH + (lane >> 4) * 16);
    const uint32_t boff = (uint32_t)(((lane & 7) + ((lane >> 4) << 3)) * APITCH +
                                     ((lane >> 3) & 1) * 16);
    const uint32_t voff = (uint32_t)(((lane & 7) + (((lane >> 3) & 1) << 3)) * APITCH +
                                     (lane >> 4) * 16);
    const uint32_t qh_base = sb + QH + (uint32_t)(wid * 16 * APITCH) + aoff;
    const uint32_t ql_base = sb + QL + (uint32_t)(wid * 16 * APITCH) + aoff;

    float o[8][4];
#pragma unroll
    for (int nj = 0; nj < 8; ++nj)
#pragma unroll
        for (int c = 0; c < 4; ++c) o[nj][c] = 0.0f;
    float m0 = -1e30f, m1 = -1e30f, l0 = 0.0f, l1 = 0.0f;

    const int ktiles = 2 * qt + 2;
    for (int jt = 0; jt < ktiles; ++jt) {
        const int k0 = jt * 64;
        __syncthreads();
        // ---- load + split K,V tiles (64 x 64 each) ----
        for (int i = tid; i < 64 * 16; i += 256) {
            const int r = i >> 4, c4 = (i & 15) << 2;
            const uint32_t off = (uint32_t)(r * APITCH + c4 * 2);
            const float4 kv = *(const float4*)(kb + (size_t)(k0 + r) * TD + c4);
            const float4 vv = *(const float4*)(vb + (size_t)(k0 + r) * TD + c4);
            {
                const __nv_bfloat16 h0 = __float2bfloat16_rn(kv.x), h1 = __float2bfloat16_rn(kv.y),
                                    h2 = __float2bfloat16_rn(kv.z), h3 = __float2bfloat16_rn(kv.w);
                *(__nv_bfloat162*)(smc + KH + off)     = __nv_bfloat162{h0, h1};
                *(__nv_bfloat162*)(smc + KH + off + 4) = __nv_bfloat162{h2, h3};
                *(__nv_bfloat162*)(smc + KL + off)     = __nv_bfloat162{
                    __float2bfloat16_rn(kv.x - __bfloat162float(h0)),
                    __float2bfloat16_rn(kv.y - __bfloat162float(h1))};
                *(__nv_bfloat162*)(smc + KL + off + 4) = __nv_bfloat162{
                    __float2bfloat16_rn(kv.z - __bfloat162float(h2)),
                    __float2bfloat16_rn(kv.w - __bfloat162float(h3))};
            }
            {
                const __nv_bfloat16 h0 = __float2bfloat16_rn(vv.x), h1 = __float2bfloat16_rn(vv.y),
                                    h2 = __float2bfloat16_rn(vv.z), h3 = __float2bfloat16_rn(vv.w);
                *(__nv_bfloat162*)(smc + VH + off)     = __nv_bfloat162{h0, h1};
                *(__nv_bfloat162*)(smc + VH + off + 4) = __nv_bfloat162{h2, h3};
                *(__nv_bfloat162*)(smc + VL + off)     = __nv_bfloat162{
                    __float2bfloat16_rn(vv.x - __bfloat162float(h0)),
                    __float2bfloat16_rn(vv.y - __bfloat162float(h1))};
                *(__nv_bfloat162*)(smc + VL + off + 4) = __nv_bfloat162{
                    __float2bfloat16_rn(vv.z - __bfloat162float(h2)),
                    __float2bfloat16_rn(vv.w - __bfloat162float(h3))};
            }
        }
        __syncthreads();

        // ---- S = Q @ K^T (bf16x3) ----
        float s[8][4];
#pragma unroll
        for (int nj = 0; nj < 8; ++nj)
#pragma unroll
            for (int c = 0; c < 4; ++c) s[nj][c] = 0.0f;

#pragma unroll
        for (int kc = 0; kc < 4; ++kc) {
            uint32_t ah[4], al[4];
            ldm4(ah, qh_base + kc * 32);
            ldm4(al, ql_base + kc * 32);
#pragma unroll
            for (int kg = 0; kg < 4; ++kg) {
                uint32_t bh[4], bl[4];
                ldm4(bh, sb + KH + (uint32_t)(kg * 16 * APITCH) + boff + kc * 32);
                ldm4(bl, sb + KL + (uint32_t)(kg * 16 * APITCH) + boff + kc * 32);
                mma16816(s[2 * kg],     ah, &bh[0]);
                mma16816(s[2 * kg],     ah, &bl[0]);
                mma16816(s[2 * kg],     al, &bh[0]);
                mma16816(s[2 * kg + 1], ah, &bh[2]);
                mma16816(s[2 * kg + 1], ah, &bl[2]);
                mma16816(s[2 * kg + 1], al, &bh[2]);
            }
        }

        // ---- scale + causal mask ----
        const int gr0 = q0 + wid * 16 + (lane >> 2);
        const int gr1 = gr0 + 8;
        if (jt >= 2 * qt) {
#pragma unroll
            for (int nj = 0; nj < 8; ++nj) {
                const int gc = k0 + nj * 8 + (lane & 3) * 2;
                s[nj][0] = (gc     > gr0) ? -10000.0f : s[nj][0] * 0.125f;
                s[nj][1] = (gc + 1 > gr0) ? -10000.0f : s[nj][1] * 0.125f;
                s[nj][2] = (gc     > gr1) ? -10000.0f : s[nj][2] * 0.125f;
                s[nj][3] = (gc + 1 > gr1) ? -10000.0f : s[nj][3] * 0.125f;
            }
        } else {
#pragma unroll
            for (int nj = 0; nj < 8; ++nj)
#pragma unroll
                for (int c = 0; c < 4; ++c) s[nj][c] *= 0.125f;
        }

        // ---- streaming softmax (rows gr0, gr1 per thread; quad-shfl reduce) ----
        float mx0 = -1e30f, mx1 = -1e30f;
#pragma unroll
        for (int nj = 0; nj < 8; ++nj) {
            mx0 = fmaxf(mx0, fmaxf(s[nj][0], s[nj][1]));
            mx1 = fmaxf(mx1, fmaxf(s[nj][2], s[nj][3]));
        }
        mx0 = fmaxf(mx0, __shfl_xor_sync(0xffffffffu, mx0, 1));
        mx0 = fmaxf(mx0, __shfl_xor_sync(0xffffffffu, mx0, 2));
        mx1 = fmaxf(mx1, __shfl_xor_sync(0xffffffffu, mx1, 1));
        mx1 = fmaxf(mx1, __shfl_xor_sync(0xffffffffu, mx1, 2));

        const float mn0 = fmaxf(m0, mx0), mn1 = fmaxf(m1, mx1);
        const float f0 = __expf(m0 - mn0), f1 = __expf(m1 - mn1);

        float rs0 = 0.0f, rs1 = 0.0f;
#pragma unroll
        for (int nj = 0; nj < 8; ++nj) {
            s[nj][0] = __expf(s[nj][0] - mn0);
            s[nj][1] = __expf(s[nj][1] - mn0);
            s[nj][2] = __expf(s[nj][2] - mn1);
            s[nj][3] = __expf(s[nj][3] - mn1);
            rs0 += s[nj][0] + s[nj][1];
            rs1 += s[nj][2] + s[nj][3];
        }
        rs0 += __shfl_xor_sync(0xffffffffu, rs0, 1);
        rs0 += __shfl_xor_sync(0xffffffffu, rs0, 2);
        rs1 += __shfl_xor_sync(0xffffffffu, rs1, 1);
        rs1 += __shfl_xor_sync(0xffffffffu, rs1, 2);

        l0 = l0 * f0 + rs0;  m0 = mn0;
        l1 = l1 * f1 + rs1;  m1 = mn1;
#pragma unroll
        for (int nj = 0; nj < 8; ++nj) {
            o[nj][0] *= f0; o[nj][1] *= f0;
            o[nj][2] *= f1; o[nj][3] *= f1;
        }

        // ---- O += P @ V (P packed in-register, bf16x3) ----
#pragma unroll
        for (int kc2 = 0; kc2 < 4; ++kc2) {
            uint32_t ph[4], pl[4];
            ph[0] = pack_bf(s[2 * kc2][0],     s[2 * kc2][1]);
            ph[1] = pack_bf(s[2 * kc2][2],     s[2 * kc2][3]);
            ph[2] = pack_bf(s[2 * kc2 + 1][0], s[2 * kc2 + 1][1]);
            ph[3] = pack_bf(s[2 * kc2 + 1][2], s[2 * kc2 + 1][3]);
            pl[0] = pack_lo(ph[0], s[2 * kc2][0],     s[2 * kc2][1]);
            pl[1] = pack_lo(ph[1], s[2 * kc2][2],     s[2 * kc2][3]);
            pl[2] = pack_lo(ph[2], s[2 * kc2 + 1][0], s[2 * kc2 + 1][1]);
            pl[3] = pack_lo(ph[3], s[2 * kc2 + 1][2], s[2 * kc2 + 1][3]);
#pragma unroll
            for (int vg = 0; vg < 4; ++vg) {
                uint32_t vh[4], vl[4];
                ldm4t(vh, sb + VH + (uint32_t)(kc2 * 16 * APITCH) + voff + vg * 32);
                ldm4t(vl, sb + VL + (uint32_t)(kc2 * 16 * APITCH) + voff + vg * 32);
                mma16816(o[2 * vg],     ph, &vh[0]);
                mma16816(o[2 * vg],     ph, &vl[0]);
                mma16816(o[2 * vg],     pl, &vh[0]);
                mma16816(o[2 * vg + 1], ph, &vh[2]);
                mma16816(o[2 * vg + 1], ph, &vl[2]);
                mma16816(o[2 * vg + 1], pl, &vh[2]);
            }
        }
    }

    // ---- epilogue: normalize, split to bf16 hi/lo, write merged-head layout ----
    const float i0 = 1.0f / l0, i1 = 1.0f / l1;
    const int r0 = q0 + wid * 16 + (lane >> 2);
    const size_t g0 = ((size_t)b * S + r0) * D + h * HD;
    const size_t g1 = g0 + (size_t)8 * D;
#pragma unroll
    for (int nj = 0; nj < 8; ++nj) {
        const int col = nj * 8 + (lane & 3) * 2;
        const float v0 = o[nj][0] * i0, v1 = o[nj][1] * i0;
        const float v2 = o[nj][2] * i1, v3 = o[nj][3] * i1;
        const __nv_bfloat16 h0 = __float2bfloat16_rn(v0), h1 = __float2bfloat16_rn(v1);
        const __nv_bfloat16 h2 = __float2bfloat16_rn(v2), h3 = __float2bfloat16_rn(v3);
        *(__nv_bfloat162*)(Ahd + g0 + col) = __nv_bfloat162{h0, h1};
        *(__nv_bfloat162*)(Ahd + g1 + col) = __nv_bfloat162{h2, h3};
        *(__nv_bfloat162*)(Ald + g0 + col) = __nv_bfloat162{
            __float2bfloat16_rn(v0 - __bfloat162float(h0)),
            __float2bfloat16_rn(v1 - __bfloat162float(h1))};
        *(__nv_bfloat162*)(Ald + g1 + col) = __nv_bfloat162{
            __float2bfloat16_rn(v2 - __bfloat162float(h2)),
            __float2bfloat16_rn(v3 - __bfloat162float(h3))};
    }
}

// =====================================================================
// launch
// =====================================================================
extern "C" void kernel_launch(void* const* d_in, const int* in_sizes, int n_in,
                              void* d_out, int out_size)
{
    const float* hs     = (const float*)d_in[0];
    const float* w_attn = (const float*)d_in[1];
    const float* b_attn = (const float*)d_in[2];
    const float* w_proj = (const float*)d_in[3];
    const float* b_proj = (const float*)d_in[4];
    float* out = (float*)d_out;

    float* qkv;
    __nv_bfloat16 *Ah, *Al, *Bh, *Bl;
    cudaGetSymbolAddress((void**)&qkv, g_qkv);
    cudaGetSymbolAddress((void**)&Ah, g_Ah);
    cudaGetSymbolAddress((void**)&Al, g_Al);
    cudaGetSymbolAddress((void**)&Bh, g_Bh);
    cudaGetSymbolAddress((void**)&Bl, g_Bl);

    cudaFuncSetAttribute(gemm_bf16x3_kernel,
                         cudaFuncAttributeMaxDynamicSharedMemorySize, GEMM_SMEM);
    cudaFuncSetAttribute(attn_mma_kernel,
                         cudaFuncAttributeMaxDynamicSharedMemorySize, ATTN2_SMEM);

    // --- stage 1: QKV projection (bf16x3 mma.sync) ---
    split_bf16_kernel<<<(M * D / 4 + 255) / 256, 256>>>(hs, Ah, Al, M * D / 4);
    transpose_split_kernel<<<dim3(TD / 32, D / 32), dim3(32, 8)>>>(w_attn, Bh, Bl, D, TD);
    dim3 g1(TD / 128, M / 128);
    gemm_bf16x3_kernel<<<g1, 256, GEMM_SMEM>>>(Ah, Al, Bh, Bl, b_attn, qkv, TD, D);

    // --- stage 2: causal attention (bf16x3 mma.sync flash) ---
    // writes Ah/Al directly (bf16 split) for the proj GEMM
    dim3 g2(S / 128, H, Bsz);          // (16, 16, 4)
    attn_mma_kernel<<<g2, 256, ATTN2_SMEM>>>(qkv, Ah, Al);

    // --- stage 3: output projection ---
    transpose_split_kernel<<<dim3(D / 32, D / 32), dim3(32, 8)>>>(w_proj, Bh, Bl, D, D);
    dim3 g3(D / 128, M / 128);
    gemm_bf16x3_kernel<<<g3, 256, GEMM_SMEM>>>(Ah, Al, Bh, Bl, b_proj, out, D, D);
}